// round 16
// baseline (speedup 1.0000x reference)
#include <cuda_runtime.h>
#include <math.h>

#define Bc 2
#define Hc 1080
#define Wc 1920
#define Kc 2048
#define Pc 256
#define NR 60      // real rows: [iy-30, iy+29]; rows 60-63 are don't-care pad
#define PITCH 68   // 68 mod 32 = 4: row- and column-walks conflict-free;
                   // 68 mod 4 = 0 keeps float4/float2 smem ops aligned.

__global__ __launch_bounds__(256)
void brief_desc_kernel(const float* __restrict__ img,
                       const float* __restrict__ kp,
                       const float* __restrict__ ori,
                       const float* __restrict__ oy1v,
                       const float* __restrict__ ox1v,
                       const float* __restrict__ oy2v,
                       const float* __restrict__ ox2v,
                       const float* __restrict__ thr,
                       const int*   __restrict__ radii,
                       float* __restrict__ out)
{
    __shared__ float S[64 * PITCH]; // 17.4 KB; rows 60-63 never initialized/used
    __shared__ float seg2[8 * 64];  // [q][column] totals, float2-accessed
    __shared__ float red[8];

    const int blk = blockIdx.x;      // b*K + k
    const int b   = blk >> 11;       // Kc = 2048
    const int tid = threadIdx.x;

    // --- minimal pre-phase state: patch origin only ---
    int iy, ix;
    {
        const float kpy = kp[blk * 2 + 0];
        const float kpx = kp[blk * 2 + 1];
        iy = (int)rintf(fminf(fmaxf(kpy, 0.0f), (float)(Hc - 1)));
        ix = (int)rintf(fminf(fmaxf(kpx, 0.0f), (float)(Wc - 1)));
    }
    const int oy0 = iy - 30;
    const int ox0 = (ix - 31) & ~3;  // 4-aligned for float4 LDG
    const float* imb = img + (size_t)b * Hc * Wc;

    // CTA-uniform: whole 60x64 patch strictly inside the image?
    const bool interior = (oy0 >= 0) & (oy0 <= Hc - NR) &
                          (ox0 >= 0) & (ox0 <= Wc - 64);

    // ===== Phase A: fused load + row prefix (coalesced float4 + shfl scan) =====
    {
        const int lane16 = tid & 15;          // chunk index within row
        const int grp    = tid >> 4;          // 16 row-groups; warp = 2 rows
        const int gxc    = ox0 + (lane16 << 2);

        // passes 0..2: rows 0..47 (all warps); pass 3: rows 48..59 (warps 0..5)
        #pragma unroll
        for (int p = 0; p < 4; p++) {
            const int r = (p << 4) + grp;
            if (p == 3 && grp >= 12) break;   // whole-warp exit (warps 6,7)
            const int gy = oy0 + r;
            float4 e;
            if (interior) {
                e = *reinterpret_cast<const float4*>(imb + (size_t)gy * Wc + gxc);
            } else {
                e = make_float4(0.f, 0.f, 0.f, 0.f);
                const bool xok = (gxc >= 0) & (gxc <= Wc - 4);
                if (xok && gy >= 0 && gy < Hc)
                    e = *reinterpret_cast<const float4*>(imb + (size_t)gy * Wc + gxc);
            }

            float v0 = e.x;
            float v1 = v0 + e.y;
            float v2 = v1 + e.z;
            float v3 = v2 + e.w;

            float t = v3;                     // inclusive scan of chunk totals
            #pragma unroll
            for (int d = 1; d < 16; d <<= 1) {
                const float n = __shfl_up_sync(0xffffffffu, t, d, 16);
                if (lane16 >= d) t += n;
            }
            const float off = t - v3;         // exclusive prefix for this chunk

            *reinterpret_cast<float4*>(&S[r * PITCH + (lane16 << 2)]) =
                make_float4(v0 + off, v1 + off, v2 + off, v3 + off);
        }
    }
    __syncthreads();

    // ===== Phase B: column prefix — float2 column pairs, 8 segments of 8 rows =====
    // q is warp-uniform (tid>>5); segment 7 includes don't-care rows 60-63
    // whose values never reach any sampled cell or any read seg total.
    {
        const int cpair = tid & 31;           // column pair: cols 2c, 2c+1
        const int q     = tid >> 5;           // segment 0..7 (warp-uniform)
        const int base  = (q << 3) * PITCH + (cpair << 1);

        float v0[8], v1[8];
        float s0 = 0.f, s1 = 0.f;
        #pragma unroll
        for (int i = 0; i < 8; i++) {
            const float2 e = *reinterpret_cast<const float2*>(&S[base + i * PITCH]);
            s0 += e.x; v0[i] = s0;
            s1 += e.y; v1[i] = s1;
        }
        *reinterpret_cast<float2*>(&seg2[(q << 6) + (cpair << 1)]) =
            make_float2(s0, s1);
        __syncthreads();

        float o0 = 0.f, o1 = 0.f;
        for (int qq = 0; qq < q; qq++) {      // warp-uniform trip count
            const float2 t = *reinterpret_cast<const float2*>(
                &seg2[(qq << 6) + (cpair << 1)]);
            o0 += t.x; o1 += t.y;
        }

        #pragma unroll
        for (int i = 0; i < 8; i++)
            *reinterpret_cast<float2*>(&S[base + i * PITCH]) =
                make_float2(v0[i] + o0, v1[i] + o1);
    }
    __syncthreads();

    // ===== Phase C: deferred keypoint/pattern state + sampling =====
    const float kpy = kp[blk * 2 + 0];        // broadcast reload (L1-hit)
    const float kpx = kp[blk * 2 + 1];
    const float valid = (kpy >= 0.0f) ? 1.0f : 0.0f;
    const float y = fminf(fmaxf(kpy, 0.0f), (float)(Hc - 1));
    const float x = fminf(fmaxf(kpx, 0.0f), (float)(Wc - 1));

    const float theta = ori[(size_t)b * Hc * Wc + (size_t)iy * Wc + ix];
    float st, ct;
    __sincosf(theta, &st, &ct);               // |theta|<=pi: err ~2^-21

    const float o_y1 = oy1v[tid];
    const float o_x1 = ox1v[tid];
    const float o_y2 = oy2v[tid];
    const float o_x2 = ox2v[tid];
    const float th   = thr[tid];
    const int   rad  = radii[tid];
    const float dn   = (float)(2 * rad + 1);
    const float invden = __fdividef(1.0f, dn * dn);   // MUFU.RCP, err 2^-22

    const float p1y = y + (o_x1 * st + o_y1 * ct);
    const float p1x = x + (o_x1 * ct - o_y1 * st);
    const float p2y = y + (o_x2 * st + o_y2 * ct);
    const float p2x = x + (o_x2 * ct - o_y2 * st);

    auto boxavg = [&](float py, float px) -> float {
        // reference order: round first, then clip
        const float jyf = fminf(fmaxf(rintf(py), 0.0f), (float)(Hc - 1));
        const float jxf = fminf(fmaxf(rintf(px), 0.0f), (float)(Wc - 1));
        const int ly = (int)jyf - oy0;        // in [7,53]
        const int lx = (int)jxf - ox0;        // in [8,57]
        const int y1 = (ly - rad - 1) * PITCH, y2 = (ly + rad) * PITCH;
        const int x1 = lx - rad - 1,           x2 = lx + rad;
        const float s = S[y2 + x2] - S[y1 + x2] - S[y2 + x1] + S[y1 + x1];
        return s * invden;
    };

    const float d = boxavg(p1y, p1x) - boxavg(p2y, p2x) - th;

    // ===== Phase D: L2 normalize + write =====
    float sq = d * d;
    #pragma unroll
    for (int off = 16; off; off >>= 1)
        sq += __shfl_xor_sync(0xffffffffu, sq, off);
    if ((tid & 31) == 0) red[tid >> 5] = sq;
    __syncthreads();
    const float tot = red[0] + red[1] + red[2] + red[3]
                    + red[4] + red[5] + red[6] + red[7];
    const float norm  = sqrtf(tot);
    const float scale = valid / fmaxf(norm, 1e-12f);

    out[(size_t)blk * Pc + tid] = d * scale;
}

extern "C" void kernel_launch(void* const* d_in, const int* in_sizes, int n_in,
                              void* d_out, int out_size)
{
    const float* img  = (const float*)d_in[0];  // image (B,1,H,W)
    const float* kp   = (const float*)d_in[1];  // keypoints (B,K,2)
    const float* ori  = (const float*)d_in[2];  // orientation (B,1,H,W)
    const float* oy1  = (const float*)d_in[3];
    const float* ox1  = (const float*)d_in[4];
    const float* oy2  = (const float*)d_in[5];
    const float* ox2  = (const float*)d_in[6];
    const float* thr  = (const float*)d_in[7];
    const int*   rad  = (const int*)d_in[8];
    float* out = (float*)d_out;

    brief_desc_kernel<<<Bc * Kc, Pc>>>(img, kp, ori, oy1, ox1, oy2, ox2, thr, rad, out);
}

// round 17
// speedup vs baseline: 1.0184x; 1.0184x over previous
#include <cuda_runtime.h>
#include <math.h>

#define Bc 2
#define Hc 1080
#define Wc 1920
#define Kc 2048
#define Pc 256
#define NR 60      // real rows: [iy-30, iy+29]; rows 60-63 are don't-care pad
#define PITCH 68   // 68 mod 32 = 4: row- and column-walks conflict-free;
                   // 68 mod 4 = 0 keeps float4/float2 smem ops aligned.

__global__ __launch_bounds__(256)
void brief_desc_kernel(const float* __restrict__ img,
                       const float* __restrict__ kp,
                       const float* __restrict__ ori,
                       const float* __restrict__ oy1v,
                       const float* __restrict__ ox1v,
                       const float* __restrict__ oy2v,
                       const float* __restrict__ ox2v,
                       const float* __restrict__ thr,
                       const int*   __restrict__ radii,
                       float* __restrict__ out)
{
    __shared__ float S[64 * PITCH]; // 17.4 KB; rows 60-63 never initialized/used
    __shared__ float seg2[8 * 64];  // [q][column] totals, float2-accessed
    __shared__ float red[8];

    const int blk = blockIdx.x;      // b*K + k
    const int b   = blk >> 11;       // Kc = 2048
    const int tid = threadIdx.x;

    // --- minimal pre-phase state: patch origin only ---
    int iy, ix;
    {
        const float kpy = kp[blk * 2 + 0];
        const float kpx = kp[blk * 2 + 1];
        iy = __float2int_rn(fminf(fmaxf(kpy, 0.0f), (float)(Hc - 1)));
        ix = __float2int_rn(fminf(fmaxf(kpx, 0.0f), (float)(Wc - 1)));
    }
    const int oy0 = iy - 30;
    const int ox0 = (ix - 31) & ~3;  // 4-aligned for float4 LDG
    const float* imb = img + (size_t)b * Hc * Wc;

    // CTA-uniform: whole 60x64 patch strictly inside the image?
    const bool interior = (oy0 >= 0) & (oy0 <= Hc - NR) &
                          (ox0 >= 0) & (ox0 <= Wc - 64);

    // ===== Phase A: fused load + row prefix (coalesced float4 + shfl scan) =====
    {
        const int lane16 = tid & 15;          // chunk index within row
        const int grp    = tid >> 4;          // 16 row-groups; warp = 2 rows
        const int gxc    = ox0 + (lane16 << 2);

        // passes 0..2: rows 0..47 (all warps); pass 3: rows 48..59 (warps 0..5)
        #pragma unroll
        for (int p = 0; p < 4; p++) {
            const int r = (p << 4) + grp;
            if (p == 3 && grp >= 12) break;   // whole-warp exit (warps 6,7)
            const int gy = oy0 + r;
            float4 e;
            if (interior) {
                e = *reinterpret_cast<const float4*>(imb + (size_t)gy * Wc + gxc);
            } else {
                e = make_float4(0.f, 0.f, 0.f, 0.f);
                const bool xok = (gxc >= 0) & (gxc <= Wc - 4);
                if (xok && gy >= 0 && gy < Hc)
                    e = *reinterpret_cast<const float4*>(imb + (size_t)gy * Wc + gxc);
            }

            float v0 = e.x;
            float v1 = v0 + e.y;
            float v2 = v1 + e.z;
            float v3 = v2 + e.w;

            float t = v3;                     // inclusive scan of chunk totals
            #pragma unroll
            for (int d = 1; d < 16; d <<= 1) {
                const float n = __shfl_up_sync(0xffffffffu, t, d, 16);
                if (lane16 >= d) t += n;
            }
            const float off = t - v3;         // exclusive prefix for this chunk

            *reinterpret_cast<float4*>(&S[r * PITCH + (lane16 << 2)]) =
                make_float4(v0 + off, v1 + off, v2 + off, v3 + off);
        }
    }
    __syncthreads();

    // ===== Phase B: column prefix — float2 column pairs, 8 segments of 8 rows =====
    // q is warp-uniform (tid>>5); segment 7 includes don't-care rows 60-63
    // whose values never reach any sampled cell or any read seg total.
    {
        const int cpair = tid & 31;           // column pair: cols 2c, 2c+1
        const int q     = tid >> 5;           // segment 0..7 (warp-uniform)
        const int base  = (q << 3) * PITCH + (cpair << 1);

        float v0[8], v1[8];
        float s0 = 0.f, s1 = 0.f;
        #pragma unroll
        for (int i = 0; i < 8; i++) {
            const float2 e = *reinterpret_cast<const float2*>(&S[base + i * PITCH]);
            s0 += e.x; v0[i] = s0;
            s1 += e.y; v1[i] = s1;
        }
        *reinterpret_cast<float2*>(&seg2[(q << 6) + (cpair << 1)]) =
            make_float2(s0, s1);
        __syncthreads();

        float o0 = 0.f, o1 = 0.f;
        for (int qq = 0; qq < q; qq++) {      // warp-uniform trip count
            const float2 t = *reinterpret_cast<const float2*>(
                &seg2[(qq << 6) + (cpair << 1)]);
            o0 += t.x; o1 += t.y;
        }

        #pragma unroll
        for (int i = 0; i < 8; i++)
            *reinterpret_cast<float2*>(&S[base + i * PITCH]) =
                make_float2(v0[i] + o0, v1[i] + o1);
    }
    __syncthreads();

    // ===== Phase C: deferred keypoint/pattern state + sampling =====
    const float kpy = kp[blk * 2 + 0];        // broadcast reload (L1-hit)
    const float kpx = kp[blk * 2 + 1];
    const float valid = (kpy >= 0.0f) ? 1.0f : 0.0f;
    const float y = fminf(fmaxf(kpy, 0.0f), (float)(Hc - 1));
    const float x = fminf(fmaxf(kpx, 0.0f), (float)(Wc - 1));

    const float theta = ori[(size_t)b * Hc * Wc + (size_t)iy * Wc + ix];
    float st, ct;
    __sincosf(theta, &st, &ct);               // |theta|<=pi: err ~2^-21

    const float o_y1 = oy1v[tid];
    const float o_x1 = ox1v[tid];
    const float o_y2 = oy2v[tid];
    const float o_x2 = ox2v[tid];
    const float th   = thr[tid];
    const int   rad  = radii[tid];
    const float dn   = (float)(2 * rad + 1);
    const float invden = __fdividef(1.0f, dn * dn);   // MUFU.RCP, err 2^-22

    const float p1y = y + (o_x1 * st + o_y1 * ct);
    const float p1x = x + (o_x1 * ct - o_y1 * st);
    const float p2y = y + (o_x2 * st + o_y2 * ct);
    const float p2x = x + (o_x2 * ct - o_y2 * st);

    auto boxavg = [&](float py, float px) -> float {
        // F2I.RN = round-half-even; round-then-clip commutes into int domain
        const int jy = min(max(__float2int_rn(py), 0), Hc - 1);
        const int jx = min(max(__float2int_rn(px), 0), Wc - 1);
        const int ly = jy - oy0;              // in [7,53]
        const int lx = jx - ox0;              // in [8,57]
        const int y1 = (ly - rad - 1) * PITCH, y2 = (ly + rad) * PITCH;
        const int x1 = lx - rad - 1,           x2 = lx + rad;
        const float s = S[y2 + x2] - S[y1 + x2] - S[y2 + x1] + S[y1 + x1];
        return s * invden;
    };

    const float d = boxavg(p1y, p1x) - boxavg(p2y, p2x) - th;

    // ===== Phase D: L2 normalize + write =====
    float sq = d * d;
    #pragma unroll
    for (int off = 16; off; off >>= 1)
        sq += __shfl_xor_sync(0xffffffffu, sq, off);
    if ((tid & 31) == 0) red[tid >> 5] = sq;
    __syncthreads();
    const float tot = red[0] + red[1] + red[2] + red[3]
                    + red[4] + red[5] + red[6] + red[7];
    // 1/max(sqrt(tot),1e-12) == rsqrt(max(tot,1e-24)) exactly (threshold maps)
    const float scale = valid * rsqrtf(fmaxf(tot, 1e-24f));

    out[(size_t)blk * Pc + tid] = d * scale;
}

extern "C" void kernel_launch(void* const* d_in, const int* in_sizes, int n_in,
                              void* d_out, int out_size)
{
    const float* img  = (const float*)d_in[0];  // image (B,1,H,W)
    const float* kp   = (const float*)d_in[1];  // keypoints (B,K,2)
    const float* ori  = (const float*)d_in[2];  // orientation (B,1,H,W)
    const float* oy1  = (const float*)d_in[3];
    const float* ox1  = (const float*)d_in[4];
    const float* oy2  = (const float*)d_in[5];
    const float* ox2  = (const float*)d_in[6];
    const float* thr  = (const float*)d_in[7];
    const int*   rad  = (const int*)d_in[8];
    float* out = (float*)d_out;

    brief_desc_kernel<<<Bc * Kc, Pc>>>(img, kp, ori, oy1, ox1, oy2, ox2, thr, rad, out);
}